// round 4
// baseline (speedup 1.0000x reference)
#include <cuda_runtime.h>
#include <stdint.h>

#define KPRE       500
#define MAXDET     300
#define SCORE_THR  0.05f
#define NMS_THR    0.5f
#define MIN_SIZE   0.01f
#define BBOX_CLAMP 4.135166556742356f   // log(1000/16)

#define HLO        0.9f
#define HBINS      64
#define HSCALE     640.0f                // HBINS / (1 - HLO)
#define CAPG       16384                 // per-class raw candidate buffer
#define KMAX       2048                  // post-threshold candidates (sortable)
#define FBINS      8192

#define NTN        512                   // nms threads
#define DYN_SMEM   57344                 // [0,32768) ioum|fhist, [32768,49152) keys, [49152,57152) cbox

#define BMAX   2
#define AMAX   131072
#define CMAX   96
#define BCMAX  192

__device__ float              g_boxes[(size_t)BMAX * AMAX * 4];
__device__ unsigned char      g_valid[(size_t)BMAX * AMAX];
__device__ unsigned long long g_keys[(size_t)BCMAX * CAPG];
__device__ unsigned int       g_cnt[BCMAX];

// ---------------------------------------------------------------------------
// K1: decode + clamp + valid mask; zero per-class counters
// ---------------------------------------------------------------------------
__global__ void rn_decode_kernel(const float* __restrict__ deltas,
                                 const float* __restrict__ anchors,
                                 const int* __restrict__ imh,
                                 const int* __restrict__ imw,
                                 int B, int A) {
    int i = blockIdx.x * blockDim.x + threadIdx.x;
    if (i < BCMAX) g_cnt[i] = 0;
    if (i >= B * A) return;
    float W = (float)imw[0];
    float H = (float)imh[0];
    float4 an = reinterpret_cast<const float4*>(anchors)[i];
    float4 dt = reinterpret_cast<const float4*>(deltas)[i];
    float aw  = an.z - an.x;
    float ah  = an.w - an.y;
    float acx = an.x + 0.5f * aw;
    float acy = an.y + 0.5f * ah;
    float dw  = fminf(dt.z, BBOX_CLAMP);
    float dh  = fminf(dt.w, BBOX_CLAMP);
    float pcx = dt.x * aw + acx;
    float pcy = dt.y * ah + acy;
    float pw  = expf(dw) * aw;
    float ph  = expf(dh) * ah;
    float x1 = fminf(fmaxf(pcx - 0.5f * pw, 0.0f), W);
    float y1 = fminf(fmaxf(pcy - 0.5f * ph, 0.0f), H);
    float x2 = fminf(fmaxf(pcx + 0.5f * pw, 0.0f), W);
    float y2 = fminf(fmaxf(pcy + 0.5f * ph, 0.0f), H);
    reinterpret_cast<float4*>(g_boxes)[i] = make_float4(x1, y1, x2, y2);
    g_valid[i] = (((x2 - x1) >= MIN_SIZE) && ((y2 - y1) >= MIN_SIZE)) ? 1 : 0;
}

// ---------------------------------------------------------------------------
// K2: single coalesced pass; push all (valid & s > HLO) into class buffers
// ---------------------------------------------------------------------------
#define CA   512     // anchors per block
#define CANT 256

__device__ __forceinline__ void rn_push_g(float s, int bc, unsigned int a) {
    unsigned int pos = atomicAdd(&g_cnt[bc], 1u);
    if (pos < CAPG)
        g_keys[(size_t)bc * CAPG + pos] =
            ((unsigned long long)__float_as_uint(s) << 32) |
            (unsigned long long)(0xFFFFFFFFu - a);
}

__global__ void __launch_bounds__(CANT)
rn_collect(const float* __restrict__ scores, int B, int A, int C) {
    int b   = blockIdx.y;
    int a0  = blockIdx.x * CA;
    int na  = min(CA, A - a0);
    int tid = threadIdx.x;
    const unsigned char* __restrict__ val = g_valid + (size_t)b * A + a0;

    if ((C & 3) == 0) {
        unsigned int C4 = (unsigned int)C >> 2;
        const float4* __restrict__ s4 =
            reinterpret_cast<const float4*>(scores + ((size_t)b * A + a0) * C);
        unsigned int n4 = (unsigned int)na * C4;

        auto proc = [&](float4 v, unsigned int i) {
            unsigned int a  = i / C4;
            unsigned int c4 = (i - a * C4) << 2;
            if (!val[a]) return;
            int bc = b * C + (int)c4;
            unsigned int ag = (unsigned int)a0 + a;
            if (v.x > HLO) rn_push_g(v.x, bc + 0, ag);
            if (v.y > HLO) rn_push_g(v.y, bc + 1, ag);
            if (v.z > HLO) rn_push_g(v.z, bc + 2, ag);
            if (v.w > HLO) rn_push_g(v.w, bc + 3, ag);
        };

        unsigned int i = (unsigned int)tid;
        for (; i + 3u * CANT < n4; i += 4u * CANT) {
            float4 v0 = s4[i];
            float4 v1 = s4[i + CANT];
            float4 v2 = s4[i + 2u * CANT];
            float4 v3 = s4[i + 3u * CANT];
            proc(v0, i);
            proc(v1, i + CANT);
            proc(v2, i + 2u * CANT);
            proc(v3, i + 3u * CANT);
        }
        for (; i < n4; i += CANT) proc(s4[i], i);
    } else {
        const float* __restrict__ s1 = scores + ((size_t)b * A + a0) * C;
        unsigned int nE = (unsigned int)na * (unsigned int)C;
        for (unsigned int i = (unsigned int)tid; i < nE; i += CANT) {
            unsigned int a = i / (unsigned int)C;
            unsigned int c = i - a * (unsigned int)C;
            float s = s1[i];
            if (val[a] && s > HLO)
                rn_push_g(s, b * C + (int)c, (unsigned int)a0 + a);
        }
    }
}

// ---------------------------------------------------------------------------
// K3: per-class threshold + refilter + sort + NMS + output
// ---------------------------------------------------------------------------
__global__ void __launch_bounds__(NTN)
rn_nms(float* __restrict__ out, const float* __restrict__ scores,
       int B, int A, int C) {
    extern __shared__ unsigned char dyn[];
    unsigned int*       ioum  = reinterpret_cast<unsigned int*>(dyn);           // [0,32000)
    unsigned int*       fhist = reinterpret_cast<unsigned int*>(dyn);           // alias, [0,32768)
    unsigned long long* keys  = reinterpret_cast<unsigned long long*>(dyn + 32768); // [KMAX]
    float4*             cbox  = reinterpret_cast<float4*>(dyn + 49152);         // [KPRE]

    __shared__ float        cscore[KPRE];
    __shared__ float        carea[KPRE];
    __shared__ unsigned int hist64[HBINS];
    __shared__ unsigned int chunk512[NTN];
    __shared__ unsigned int keep0[16], keepw[16], pref[16];
    __shared__ unsigned int s_m, s_kk, s_nkeep;
    __shared__ int          s_fb;

    const int tid = threadIdx.x;
    const int bc  = blockIdx.x;
    const int b   = bc / C;
    const int c   = bc % C;

    unsigned int n_raw = g_cnt[bc];
    const unsigned long long* __restrict__ gk = g_keys + (size_t)bc * CAPG;

    if (tid == 0) {
        s_fb = (n_raw < KPRE) || (n_raw > CAPG);
        s_m  = 0;
    }
    if (tid < HBINS) hist64[tid] = 0;
    if (tid < 16) keep0[tid] = 0;
    __syncthreads();

    // ---------------- fast path: threshold from buffered keys ----------------
    if (!s_fb) {
        for (unsigned int i = tid; i < n_raw; i += NTN) {
            float s = __uint_as_float((unsigned int)(gk[i] >> 32));
            int bin = min((int)((s - HLO) * HSCALE), HBINS - 1);
            atomicAdd(&hist64[bin], 1u);
        }
        __syncthreads();
        if (tid == 0) {
            unsigned int cum = 0;
            int kk = 0;
            for (int k = HBINS - 1; k >= 0; k--) {
                cum += hist64[k];
                if (cum >= KPRE) { kk = k; break; }
            }
            if (cum > KMAX) s_fb = 1;     // pathological spike -> exact path
            s_kk = (unsigned int)kk;
        }
        __syncthreads();
        if (!s_fb) {
            unsigned int kk = s_kk;
            for (unsigned int i = tid; i < n_raw; i += NTN) {
                unsigned long long key = gk[i];
                float s = __uint_as_float((unsigned int)(key >> 32));
                unsigned int bin =
                    (unsigned int)min((int)((s - HLO) * HSCALE), HBINS - 1);
                if (bin >= kk) {
                    unsigned int pos = atomicAdd(&s_m, 1u);
                    if (pos < KMAX) keys[pos] = key;
                }
            }
        }
        __syncthreads();
    }

    // ---------------- fallback: exact strided selection (rare) ---------------
    if (s_fb) {
        for (int i = tid; i < FBINS; i += NTN) fhist[i] = 0;
        if (tid == 0) s_m = 0;
        __syncthreads();
        for (int a = tid; a < A; a += NTN) {
            float s = scores[((size_t)b * A + a) * (size_t)C + c];
            if (g_valid[(size_t)b * A + a] && s > SCORE_THR) {
                int bin = min(max((int)(s * (float)FBINS), 0), FBINS - 1);
                atomicAdd(&fhist[bin], 1u);
            }
        }
        __syncthreads();
        {
            unsigned int cs = 0;
            const int per = FBINS / NTN;
            #pragma unroll
            for (int i = 0; i < FBINS / NTN; i++) cs += fhist[tid * per + i];
            chunk512[tid] = cs;
        }
        __syncthreads();
        if (tid == 0) {
            const int per = FBINS / NTN;
            unsigned int cum = 0;
            int cc;
            for (cc = NTN - 1; cc >= 0; cc--) {
                if (cum + chunk512[cc] >= KPRE) break;
                cum += chunk512[cc];
            }
            int kk = 0;
            if (cc >= 0) {
                int bs = cc * per;
                for (int bb = bs + per - 1; bb >= bs; bb--) {
                    cum += fhist[bb];
                    if (cum >= KPRE) { kk = bb; break; }
                }
            }
            while (cum > KMAX && kk < FBINS - 1) { cum -= fhist[kk]; kk++; }
            s_kk = (unsigned int)kk;
        }
        __syncthreads();
        unsigned int kk = s_kk;
        for (int a = tid; a < A; a += NTN) {
            float s = scores[((size_t)b * A + a) * (size_t)C + c];
            if (g_valid[(size_t)b * A + a] && s > SCORE_THR) {
                unsigned int bin =
                    (unsigned int)min((int)(s * (float)FBINS), FBINS - 1);
                if (bin >= kk) {
                    unsigned int pos = atomicAdd(&s_m, 1u);
                    if (pos < KMAX)
                        keys[pos] =
                            ((unsigned long long)__float_as_uint(s) << 32) |
                            (unsigned long long)(0xFFFFFFFFu - (unsigned int)a);
                }
            }
        }
        __syncthreads();
    }

    // ---------------- sort (bitonic, 1024 or 2048) ----------------
    unsigned int m = min(s_m, (unsigned int)KMAX);
    const int NSORT = (m <= 1024u) ? 1024 : 2048;
    for (int i = tid; i < NSORT; i += NTN)
        if (i >= (int)m) keys[i] = 0ULL;
    __syncthreads();

    for (int k = 2; k <= NSORT; k <<= 1) {
        for (int j = k >> 1; j > 0; j >>= 1) {
            for (int i = tid; i < NSORT; i += NTN) {
                int ixj = i ^ j;
                if (ixj > i) {
                    unsigned long long x = keys[i];
                    unsigned long long y = keys[ixj];
                    bool desc = ((i & k) == 0);
                    if (desc ? (x < y) : (x > y)) { keys[i] = y; keys[ixj] = x; }
                }
            }
            __syncthreads();
        }
    }

    // ---------------- candidate setup ----------------
    if (tid < KPRE) {
        unsigned long long key = keys[tid];
        float s = __uint_as_float((unsigned int)(key >> 32));
        unsigned int aidx = 0xFFFFFFFFu - (unsigned int)(key & 0xFFFFFFFFull);
        bool cv = (s > SCORE_THR);
        cscore[tid] = s;
        float4 bx = make_float4(0.0f, 0.0f, 0.0f, 0.0f);
        if (cv) bx = reinterpret_cast<const float4*>(g_boxes)[(size_t)b * A + aidx];
        cbox[tid]  = bx;
        carea[tid] = (bx.z - bx.x) * (bx.w - bx.y);
        if (cv) atomicOr(&keep0[tid >> 5], 1u << (tid & 31));
    }
    __syncthreads();   // fhist/keys phases done; ioum region reused now

    // ---------------- IoU mask: warp per 8 rows, ballot per 32-col chunk -----
    {
        const int lane = tid & 31;
        const int wrp  = tid >> 5;
        for (int g = wrp; g * 8 < KPRE; g += NTN / 32) {
            int i0 = g * 8;
            float4 bi[8];
            float  ai[8];
            #pragma unroll
            for (int r = 0; r < 8; r++) {
                int i = i0 + r;
                if (i < KPRE) { bi[r] = cbox[i]; ai[r] = carea[i]; }
                else { bi[r] = make_float4(0, 0, 0, 0); ai[r] = 0.0f; }
            }
            for (int ch = 0; ch < 16; ch++) {
                int j = ch * 32 + lane;
                float4 bj = (j < KPRE) ? cbox[j] : make_float4(0, 0, 0, 0);
                float  aj = (j < KPRE) ? carea[j] : 0.0f;
                #pragma unroll
                for (int r = 0; r < 8; r++) {
                    int i = i0 + r;
                    float lx = fmaxf(bi[r].x, bj.x);
                    float ly = fmaxf(bi[r].y, bj.y);
                    float rx = fminf(bi[r].z, bj.z);
                    float ry = fminf(bi[r].w, bj.w);
                    float iw = fmaxf(rx - lx, 0.0f);
                    float ih = fmaxf(ry - ly, 0.0f);
                    float inter = iw * ih;
                    float iou = inter / fmaxf(ai[r] + aj - inter, 1e-9f);
                    bool pred = (j < KPRE) && (j > i) && (iou > NMS_THR);
                    unsigned int mask = __ballot_sync(0xFFFFFFFFu, pred);
                    if (lane == r && i < KPRE) ioum[i * 16 + ch] = mask;
                }
            }
        }
    }
    __syncthreads();

    // ---------------- serial-semantics NMS scan (16 lanes, ffs skip) --------
    if (tid < 16) {
        unsigned int kw = keep0[tid];
        int kept = 0;
        for (int w = 0; w < 16; w++) {
            int p = 0;
            while (p < 32) {
                unsigned int word = __shfl_sync(0xFFFFu, kw, w);
                unsigned int rem  = (p < 32) ? (word & (0xFFFFFFFFu << p)) : 0u;
                if (!rem) break;
                int bit = __ffs(rem) - 1;
                int i = w * 32 + bit;
                kw &= ~ioum[i * 16 + tid];
                p = bit + 1;
                kept++;
                if (kept >= MAXDET) break;   // first MAXDET ranks fixed
            }
            if (kept >= MAXDET) break;
        }
        keepw[tid] = kw;
        unsigned int pc = __popc(kw);
        unsigned int scan = pc;
        #pragma unroll
        for (int o = 1; o < 16; o <<= 1) {
            unsigned int v = __shfl_up_sync(0xFFFFu, scan, o);
            if (tid >= o) scan += v;
        }
        pref[tid] = scan - pc;
        if (tid == 15) s_nkeep = scan;
    }
    __syncthreads();

    // ---------------- output ----------------
    float* outp = out + (size_t)bc * MAXDET * 5;
    if (tid < KPRE) {
        unsigned int kw = keepw[tid >> 5];
        if ((kw >> (tid & 31)) & 1u) {
            unsigned int rank = pref[tid >> 5] + __popc(kw & ((1u << (tid & 31)) - 1u));
            if (rank < MAXDET) {
                float4 bx = cbox[tid];
                outp[rank * 5 + 0] = bx.x;
                outp[rank * 5 + 1] = bx.y;
                outp[rank * 5 + 2] = bx.z;
                outp[rank * 5 + 3] = bx.w;
                outp[rank * 5 + 4] = cscore[tid];
            }
        }
    }
    unsigned int nk = min(s_nkeep, (unsigned int)MAXDET);
    for (int r = (int)nk + tid; r < MAXDET; r += NTN) {
        outp[r * 5 + 0] = 0.0f;
        outp[r * 5 + 1] = 0.0f;
        outp[r * 5 + 2] = 0.0f;
        outp[r * 5 + 3] = 0.0f;
        outp[r * 5 + 4] = -1.0f;
    }
}

// ---------------------------------------------------------------------------
// host launch
// ---------------------------------------------------------------------------
extern "C" void kernel_launch(void* const* d_in, const int* in_sizes, int n_in,
                              void* d_out, int out_size) {
    const float* deltas  = (const float*)d_in[0];
    const float* scores  = (const float*)d_in[1];
    const float* anchors = (const float*)d_in[2];
    const int*   imh     = (const int*)d_in[3];
    const int*   imw     = (const int*)d_in[4];

    long long nd = in_sizes[0];
    long long ns = in_sizes[1];
    int C  = (int)(ns * 4 / nd);
    int BC = out_size / (MAXDET * 5);
    int B  = BC / C;
    int A  = (int)(nd / (4LL * B));

    float* out = (float*)d_out;

    int n = B * A;
    rn_decode_kernel<<<(n + 255) / 256, 256>>>(deltas, anchors, imh, imw, B, A);

    dim3 cg((A + CA - 1) / CA, B);
    rn_collect<<<cg, CANT>>>(scores, B, A, C);

    cudaFuncSetAttribute(rn_nms, cudaFuncAttributeMaxDynamicSharedMemorySize, DYN_SMEM);
    rn_nms<<<BC, NTN, DYN_SMEM>>>(out, scores, B, A, C);
}

// round 5
// speedup vs baseline: 2.6091x; 2.6091x over previous
#include <cuda_runtime.h>
#include <stdint.h>

#define KPRE       500
#define MAXDET     300
#define SCORE_THR  0.05f
#define NMS_THR    0.5f
#define MIN_SIZE   0.01f
#define BBOX_CLAMP 4.135166556742356f   // log(1000/16)

#define HLO        0.99f
#define HBINS      64
#define HSCALE     6400.0f               // HBINS / (1 - HLO)
#define CAPG       16384                 // per-class raw candidate buffer
#define KMAX       2048                  // post-threshold candidates (sortable)
#define FBINS      8192

#define NTN        512                   // nms threads
#define DYN_SMEM   57344                 // [0,32768) ioum|fhist, [32768,49152) keys, [49152,57152) cbox

#define BMAX   2
#define AMAX   131072
#define CMAX   96
#define BCMAX  192

__device__ float              g_boxes[(size_t)BMAX * AMAX * 4];
__device__ unsigned char      g_valid[(size_t)BMAX * AMAX];
__device__ unsigned long long g_keys[(size_t)BCMAX * CAPG];
__device__ unsigned int       g_cnt[BCMAX];

// ---------------------------------------------------------------------------
// K1: decode + clamp + valid mask; zero per-class counters
// ---------------------------------------------------------------------------
__global__ void rn_decode_kernel(const float* __restrict__ deltas,
                                 const float* __restrict__ anchors,
                                 const int* __restrict__ imh,
                                 const int* __restrict__ imw,
                                 int B, int A) {
    int i = blockIdx.x * blockDim.x + threadIdx.x;
    if (i < BCMAX) g_cnt[i] = 0;
    if (i >= B * A) return;
    float W = (float)imw[0];
    float H = (float)imh[0];
    float4 an = reinterpret_cast<const float4*>(anchors)[i];
    float4 dt = reinterpret_cast<const float4*>(deltas)[i];
    float aw  = an.z - an.x;
    float ah  = an.w - an.y;
    float acx = an.x + 0.5f * aw;
    float acy = an.y + 0.5f * ah;
    float dw  = fminf(dt.z, BBOX_CLAMP);
    float dh  = fminf(dt.w, BBOX_CLAMP);
    float pcx = dt.x * aw + acx;
    float pcy = dt.y * ah + acy;
    float pw  = expf(dw) * aw;
    float ph  = expf(dh) * ah;
    float x1 = fminf(fmaxf(pcx - 0.5f * pw, 0.0f), W);
    float y1 = fminf(fmaxf(pcy - 0.5f * ph, 0.0f), H);
    float x2 = fminf(fmaxf(pcx + 0.5f * pw, 0.0f), W);
    float y2 = fminf(fmaxf(pcy + 0.5f * ph, 0.0f), H);
    reinterpret_cast<float4*>(g_boxes)[i] = make_float4(x1, y1, x2, y2);
    g_valid[i] = (((x2 - x1) >= MIN_SIZE) && ((y2 - y1) >= MIN_SIZE)) ? 1 : 0;
}

// ---------------------------------------------------------------------------
// K2: single coalesced pass; push all (valid & s > HLO) into class buffers
// ---------------------------------------------------------------------------
#define CA   512     // anchors per block
#define CANT 256

__device__ __forceinline__ void rn_push_g(float s, int bc, unsigned int a) {
    unsigned int pos = atomicAdd(&g_cnt[bc], 1u);
    if (pos < CAPG)
        g_keys[(size_t)bc * CAPG + pos] =
            ((unsigned long long)__float_as_uint(s) << 32) |
            (unsigned long long)(0xFFFFFFFFu - a);
}

__global__ void __launch_bounds__(CANT)
rn_collect(const float* __restrict__ scores, int B, int A, int C) {
    int b   = blockIdx.y;
    int a0  = blockIdx.x * CA;
    int na  = min(CA, A - a0);
    int tid = threadIdx.x;
    const unsigned char* __restrict__ val = g_valid + (size_t)b * A + a0;

    if ((C & 3) == 0) {
        unsigned int C4 = (unsigned int)C >> 2;
        const float4* __restrict__ s4 =
            reinterpret_cast<const float4*>(scores + ((size_t)b * A + a0) * C);
        unsigned int n4 = (unsigned int)na * C4;

        auto proc = [&](float4 v, unsigned int i) {
            if (!(v.x > HLO) && !(v.y > HLO) && !(v.z > HLO) && !(v.w > HLO))
                return;                          // fast reject (99% of vectors)
            unsigned int a  = i / C4;
            unsigned int c4 = (i - a * C4) << 2;
            if (!val[a]) return;
            int bc = b * C + (int)c4;
            unsigned int ag = (unsigned int)a0 + a;
            if (v.x > HLO) rn_push_g(v.x, bc + 0, ag);
            if (v.y > HLO) rn_push_g(v.y, bc + 1, ag);
            if (v.z > HLO) rn_push_g(v.z, bc + 2, ag);
            if (v.w > HLO) rn_push_g(v.w, bc + 3, ag);
        };

        unsigned int i = (unsigned int)tid;
        for (; i + 3u * CANT < n4; i += 4u * CANT) {
            float4 v0 = s4[i];
            float4 v1 = s4[i + CANT];
            float4 v2 = s4[i + 2u * CANT];
            float4 v3 = s4[i + 3u * CANT];
            proc(v0, i);
            proc(v1, i + CANT);
            proc(v2, i + 2u * CANT);
            proc(v3, i + 3u * CANT);
        }
        for (; i < n4; i += CANT) proc(s4[i], i);
    } else {
        const float* __restrict__ s1 = scores + ((size_t)b * A + a0) * C;
        unsigned int nE = (unsigned int)na * (unsigned int)C;
        for (unsigned int i = (unsigned int)tid; i < nE; i += CANT) {
            unsigned int a = i / (unsigned int)C;
            unsigned int c = i - a * (unsigned int)C;
            float s = s1[i];
            if (val[a] && s > HLO)
                rn_push_g(s, b * C + (int)c, (unsigned int)a0 + a);
        }
    }
}

// ---------------------------------------------------------------------------
// K3: per-class threshold + refilter + sort + NMS + output
// ---------------------------------------------------------------------------
__global__ void __launch_bounds__(NTN)
rn_nms(float* __restrict__ out, const float* __restrict__ scores,
       int B, int A, int C) {
    extern __shared__ unsigned char dyn[];
    unsigned int*       ioum  = reinterpret_cast<unsigned int*>(dyn);           // [0,32000)
    unsigned int*       fhist = reinterpret_cast<unsigned int*>(dyn);           // alias, [0,32768)
    unsigned long long* keys  = reinterpret_cast<unsigned long long*>(dyn + 32768); // [KMAX]
    float4*             cbox  = reinterpret_cast<float4*>(dyn + 49152);         // [KPRE]

    __shared__ float        cscore[KPRE];
    __shared__ float        carea[KPRE];
    __shared__ unsigned int hist64[HBINS];
    __shared__ unsigned int chunk512[NTN];
    __shared__ unsigned int keep0[16], keepw[16], pref[16];
    __shared__ unsigned int s_m, s_kk, s_nkeep;
    __shared__ int          s_fb;

    const int tid = threadIdx.x;
    const int bc  = blockIdx.x;
    const int b   = bc / C;
    const int c   = bc % C;

    unsigned int n_raw = g_cnt[bc];
    const unsigned long long* __restrict__ gk = g_keys + (size_t)bc * CAPG;

    if (tid == 0) {
        s_fb = (n_raw < KPRE) || (n_raw > CAPG);
        s_m  = 0;
    }
    if (tid < HBINS) hist64[tid] = 0;
    if (tid < 16) keep0[tid] = 0;
    __syncthreads();

    // ---------------- fast path: threshold from buffered keys ----------------
    if (!s_fb) {
        for (unsigned int i = tid; i < n_raw; i += NTN) {
            float s = __uint_as_float((unsigned int)(gk[i] >> 32));
            int bin = min((int)((s - HLO) * HSCALE), HBINS - 1);
            atomicAdd(&hist64[bin], 1u);
        }
        __syncthreads();
        if (tid == 0) {
            unsigned int cum = 0;
            int kk = 0;
            for (int k = HBINS - 1; k >= 0; k--) {
                cum += hist64[k];
                if (cum >= KPRE) { kk = k; break; }
            }
            if (cum > KMAX) s_fb = 1;     // pathological spike -> exact path
            s_kk = (unsigned int)kk;
        }
        __syncthreads();
        if (!s_fb) {
            unsigned int kk = s_kk;
            for (unsigned int i = tid; i < n_raw; i += NTN) {
                unsigned long long key = gk[i];
                float s = __uint_as_float((unsigned int)(key >> 32));
                unsigned int bin =
                    (unsigned int)min((int)((s - HLO) * HSCALE), HBINS - 1);
                if (bin >= kk) {
                    unsigned int pos = atomicAdd(&s_m, 1u);
                    if (pos < KMAX) keys[pos] = key;
                }
            }
        }
        __syncthreads();
    }

    // ---------------- fallback: exact strided selection (rare) ---------------
    if (s_fb) {
        for (int i = tid; i < FBINS; i += NTN) fhist[i] = 0;
        if (tid == 0) s_m = 0;
        __syncthreads();
        for (int a = tid; a < A; a += NTN) {
            float s = scores[((size_t)b * A + a) * (size_t)C + c];
            if (g_valid[(size_t)b * A + a] && s > SCORE_THR) {
                int bin = min(max((int)(s * (float)FBINS), 0), FBINS - 1);
                atomicAdd(&fhist[bin], 1u);
            }
        }
        __syncthreads();
        {
            unsigned int cs = 0;
            const int per = FBINS / NTN;
            #pragma unroll
            for (int i = 0; i < FBINS / NTN; i++) cs += fhist[tid * per + i];
            chunk512[tid] = cs;
        }
        __syncthreads();
        if (tid == 0) {
            const int per = FBINS / NTN;
            unsigned int cum = 0;
            int cc;
            for (cc = NTN - 1; cc >= 0; cc--) {
                if (cum + chunk512[cc] >= KPRE) break;
                cum += chunk512[cc];
            }
            int kk = 0;
            if (cc >= 0) {
                int bs = cc * per;
                for (int bb = bs + per - 1; bb >= bs; bb--) {
                    cum += fhist[bb];
                    if (cum >= KPRE) { kk = bb; break; }
                }
            }
            while (cum > KMAX && kk < FBINS - 1) { cum -= fhist[kk]; kk++; }
            s_kk = (unsigned int)kk;
        }
        __syncthreads();
        unsigned int kk = s_kk;
        for (int a = tid; a < A; a += NTN) {
            float s = scores[((size_t)b * A + a) * (size_t)C + c];
            if (g_valid[(size_t)b * A + a] && s > SCORE_THR) {
                unsigned int bin =
                    (unsigned int)min((int)(s * (float)FBINS), FBINS - 1);
                if (bin >= kk) {
                    unsigned int pos = atomicAdd(&s_m, 1u);
                    if (pos < KMAX)
                        keys[pos] =
                            ((unsigned long long)__float_as_uint(s) << 32) |
                            (unsigned long long)(0xFFFFFFFFu - (unsigned int)a);
                }
            }
        }
        __syncthreads();
    }

    // ---------------- sort (bitonic, 1024 or 2048) ----------------
    unsigned int m = min(s_m, (unsigned int)KMAX);
    const int NSORT = (m <= 1024u) ? 1024 : 2048;
    for (int i = tid; i < NSORT; i += NTN)
        if (i >= (int)m) keys[i] = 0ULL;
    __syncthreads();

    for (int k = 2; k <= NSORT; k <<= 1) {
        for (int j = k >> 1; j > 0; j >>= 1) {
            for (int i = tid; i < NSORT; i += NTN) {
                int ixj = i ^ j;
                if (ixj > i) {
                    unsigned long long x = keys[i];
                    unsigned long long y = keys[ixj];
                    bool desc = ((i & k) == 0);
                    if (desc ? (x < y) : (x > y)) { keys[i] = y; keys[ixj] = x; }
                }
            }
            __syncthreads();
        }
    }

    // ---------------- candidate setup ----------------
    if (tid < KPRE) {
        unsigned long long key = keys[tid];
        float s = __uint_as_float((unsigned int)(key >> 32));
        unsigned int aidx = 0xFFFFFFFFu - (unsigned int)(key & 0xFFFFFFFFull);
        bool cv = (s > SCORE_THR);
        cscore[tid] = s;
        float4 bx = make_float4(0.0f, 0.0f, 0.0f, 0.0f);
        if (cv) bx = reinterpret_cast<const float4*>(g_boxes)[(size_t)b * A + aidx];
        cbox[tid]  = bx;
        carea[tid] = (bx.z - bx.x) * (bx.w - bx.y);
        if (cv) atomicOr(&keep0[tid >> 5], 1u << (tid & 31));
    }
    __syncthreads();   // fhist/keys phases done; ioum region reused now

    // ---------------- IoU mask: warp per 8 rows, ballot per 32-col chunk -----
    {
        const int lane = tid & 31;
        const int wrp  = tid >> 5;
        for (int g = wrp; g * 8 < KPRE; g += NTN / 32) {
            int i0 = g * 8;
            float4 bi[8];
            float  ai[8];
            #pragma unroll
            for (int r = 0; r < 8; r++) {
                int i = i0 + r;
                if (i < KPRE) { bi[r] = cbox[i]; ai[r] = carea[i]; }
                else { bi[r] = make_float4(0, 0, 0, 0); ai[r] = 0.0f; }
            }
            for (int ch = 0; ch < 16; ch++) {
                int j = ch * 32 + lane;
                float4 bj = (j < KPRE) ? cbox[j] : make_float4(0, 0, 0, 0);
                float  aj = (j < KPRE) ? carea[j] : 0.0f;
                #pragma unroll
                for (int r = 0; r < 8; r++) {
                    int i = i0 + r;
                    float lx = fmaxf(bi[r].x, bj.x);
                    float ly = fmaxf(bi[r].y, bj.y);
                    float rx = fminf(bi[r].z, bj.z);
                    float ry = fminf(bi[r].w, bj.w);
                    float iw = fmaxf(rx - lx, 0.0f);
                    float ih = fmaxf(ry - ly, 0.0f);
                    float inter = iw * ih;
                    float iou = inter / fmaxf(ai[r] + aj - inter, 1e-9f);
                    bool pred = (j < KPRE) && (j > i) && (iou > NMS_THR);
                    unsigned int mask = __ballot_sync(0xFFFFFFFFu, pred);
                    if (lane == r && i < KPRE) ioum[i * 16 + ch] = mask;
                }
            }
        }
    }
    __syncthreads();

    // ---------------- serial NMS scan: uniform control, visits kept bits only
    if (tid < 16) {
        unsigned int kw = keep0[tid];
        int kept = 0;
        for (int w = 0; w < 16 && kept < MAXDET; w++) {
            unsigned int p = 0;
            while (true) {
                unsigned int cur = __shfl_sync(0xFFFFu, kw, w);   // refreshed word
                unsigned int rem = (p < 32u) ? (cur & (p ? (0xFFFFFFFFu << p) : 0xFFFFFFFFu)) : 0u;
                if (!rem) break;                 // uniform: rem identical on all lanes
                int bit = __ffs(rem) - 1;
                int i = w * 32 + bit;
                kw &= ~ioum[i * 16 + tid];
                kept++;
                if (kept >= MAXDET) break;       // ranks 0..299 already final
                p = (unsigned int)bit + 1u;
            }
        }
        keepw[tid] = kw;
        unsigned int pc = __popc(kw);
        unsigned int scan = pc;
        #pragma unroll
        for (int o = 1; o < 16; o <<= 1) {
            unsigned int v = __shfl_up_sync(0xFFFFu, scan, o);
            if (tid >= o) scan += v;
        }
        pref[tid] = scan - pc;
        if (tid == 15) s_nkeep = scan;
    }
    __syncthreads();

    // ---------------- output ----------------
    float* outp = out + (size_t)bc * MAXDET * 5;
    if (tid < KPRE) {
        unsigned int kw = keepw[tid >> 5];
        if ((kw >> (tid & 31)) & 1u) {
            unsigned int rank = pref[tid >> 5] + __popc(kw & ((1u << (tid & 31)) - 1u));
            if (rank < MAXDET) {
                float4 bx = cbox[tid];
                outp[rank * 5 + 0] = bx.x;
                outp[rank * 5 + 1] = bx.y;
                outp[rank * 5 + 2] = bx.z;
                outp[rank * 5 + 3] = bx.w;
                outp[rank * 5 + 4] = cscore[tid];
            }
        }
    }
    unsigned int nk = min(s_nkeep, (unsigned int)MAXDET);
    for (int r = (int)nk + tid; r < MAXDET; r += NTN) {
        outp[r * 5 + 0] = 0.0f;
        outp[r * 5 + 1] = 0.0f;
        outp[r * 5 + 2] = 0.0f;
        outp[r * 5 + 3] = 0.0f;
        outp[r * 5 + 4] = -1.0f;
    }
}

// ---------------------------------------------------------------------------
// host launch
// ---------------------------------------------------------------------------
extern "C" void kernel_launch(void* const* d_in, const int* in_sizes, int n_in,
                              void* d_out, int out_size) {
    const float* deltas  = (const float*)d_in[0];
    const float* scores  = (const float*)d_in[1];
    const float* anchors = (const float*)d_in[2];
    const int*   imh     = (const int*)d_in[3];
    const int*   imw     = (const int*)d_in[4];

    long long nd = in_sizes[0];
    long long ns = in_sizes[1];
    int C  = (int)(ns * 4 / nd);
    int BC = out_size / (MAXDET * 5);
    int B  = BC / C;
    int A  = (int)(nd / (4LL * B));

    float* out = (float*)d_out;

    int n = B * A;
    rn_decode_kernel<<<(n + 255) / 256, 256>>>(deltas, anchors, imh, imw, B, A);

    dim3 cg((A + CA - 1) / CA, B);
    rn_collect<<<cg, CANT>>>(scores, B, A, C);

    cudaFuncSetAttribute(rn_nms, cudaFuncAttributeMaxDynamicSharedMemorySize, DYN_SMEM);
    rn_nms<<<BC, NTN, DYN_SMEM>>>(out, scores, B, A, C);
}

// round 6
// speedup vs baseline: 2.9587x; 1.1340x over previous
#include <cuda_runtime.h>
#include <stdint.h>

#define KPRE       500
#define MAXDET     300
#define SCORE_THR  0.05f
#define NMS_THR    0.5f
#define MIN_SIZE   0.01f
#define BBOX_CLAMP 4.135166556742356f   // log(1000/16)

#define HLO        0.99f
#define HBINS      64
#define HSCALE     6400.0f               // HBINS / (1 - HLO)
#define CAPG       16384
#define KMAX       2048
#define FBINS      8192

#define BMAX   2
#define AMAX   131072
#define CMAX   96
#define BCMAX  192

__device__ float              g_boxes[(size_t)BMAX * AMAX * 4];
__device__ unsigned char      g_valid[(size_t)BMAX * AMAX];
__device__ unsigned long long g_keys[(size_t)BCMAX * CAPG];
__device__ unsigned int       g_cnt[BCMAX];
__device__ unsigned long long g_top[(size_t)BCMAX * 512];
__device__ unsigned int       g_ioum[(size_t)BCMAX * KPRE * 16];

// ---------------------------------------------------------------------------
// K1: decode + clamp + valid mask; zero per-class counters
// ---------------------------------------------------------------------------
__global__ void rn_decode(const float* __restrict__ deltas,
                          const float* __restrict__ anchors,
                          const int* __restrict__ imh,
                          const int* __restrict__ imw,
                          int B, int A) {
    int i = blockIdx.x * blockDim.x + threadIdx.x;
    if (i < BCMAX) g_cnt[i] = 0;
    if (i >= B * A) return;
    float W = (float)imw[0];
    float H = (float)imh[0];
    float4 an = reinterpret_cast<const float4*>(anchors)[i];
    float4 dt = reinterpret_cast<const float4*>(deltas)[i];
    float aw  = an.z - an.x;
    float ah  = an.w - an.y;
    float acx = an.x + 0.5f * aw;
    float acy = an.y + 0.5f * ah;
    float dw  = fminf(dt.z, BBOX_CLAMP);
    float dh  = fminf(dt.w, BBOX_CLAMP);
    float pcx = dt.x * aw + acx;
    float pcy = dt.y * ah + acy;
    float pw  = expf(dw) * aw;
    float ph  = expf(dh) * ah;
    float x1 = fminf(fmaxf(pcx - 0.5f * pw, 0.0f), W);
    float y1 = fminf(fmaxf(pcy - 0.5f * ph, 0.0f), H);
    float x2 = fminf(fmaxf(pcx + 0.5f * pw, 0.0f), W);
    float y2 = fminf(fmaxf(pcy + 0.5f * ph, 0.0f), H);
    reinterpret_cast<float4*>(g_boxes)[i] = make_float4(x1, y1, x2, y2);
    g_valid[i] = (((x2 - x1) >= MIN_SIZE) && ((y2 - y1) >= MIN_SIZE)) ? 1 : 0;
}

// ---------------------------------------------------------------------------
// K2: single coalesced pass; push (valid & s > HLO) into class buffers
// ---------------------------------------------------------------------------
#define CA   256     // anchors per block
#define CANT 256

__device__ __forceinline__ void rn_push_g(float s, int bc, unsigned int a) {
    unsigned int pos = atomicAdd(&g_cnt[bc], 1u);
    if (pos < CAPG)
        g_keys[(size_t)bc * CAPG + pos] =
            ((unsigned long long)__float_as_uint(s) << 32) |
            (unsigned long long)(0xFFFFFFFFu - a);
}

__global__ void __launch_bounds__(CANT)
rn_collect(const float* __restrict__ scores, int B, int A, int C) {
    int b   = blockIdx.y;
    int a0  = blockIdx.x * CA;
    int na  = min(CA, A - a0);
    int tid = threadIdx.x;
    const unsigned char* __restrict__ val = g_valid + (size_t)b * A + a0;

    if ((C & 3) == 0) {
        unsigned int C4 = (unsigned int)C >> 2;
        const float4* __restrict__ s4 =
            reinterpret_cast<const float4*>(scores + ((size_t)b * A + a0) * C);
        unsigned int n4 = (unsigned int)na * C4;

        auto proc = [&](float4 v, unsigned int i) {
            if (!(v.x > HLO) && !(v.y > HLO) && !(v.z > HLO) && !(v.w > HLO))
                return;
            unsigned int a  = i / C4;
            unsigned int c4 = (i - a * C4) << 2;
            if (!val[a]) return;
            int bc = b * C + (int)c4;
            unsigned int ag = (unsigned int)a0 + a;
            if (v.x > HLO) rn_push_g(v.x, bc + 0, ag);
            if (v.y > HLO) rn_push_g(v.y, bc + 1, ag);
            if (v.z > HLO) rn_push_g(v.z, bc + 2, ag);
            if (v.w > HLO) rn_push_g(v.w, bc + 3, ag);
        };

        unsigned int i = (unsigned int)tid;
        for (; i + 3u * CANT < n4; i += 4u * CANT) {
            float4 v0 = __ldcs(&s4[i]);
            float4 v1 = __ldcs(&s4[i + CANT]);
            float4 v2 = __ldcs(&s4[i + 2u * CANT]);
            float4 v3 = __ldcs(&s4[i + 3u * CANT]);
            proc(v0, i);
            proc(v1, i + CANT);
            proc(v2, i + 2u * CANT);
            proc(v3, i + 3u * CANT);
        }
        for (; i < n4; i += CANT) proc(__ldcs(&s4[i]), i);
    } else {
        const float* __restrict__ s1 = scores + ((size_t)b * A + a0) * C;
        unsigned int nE = (unsigned int)na * (unsigned int)C;
        for (unsigned int i = (unsigned int)tid; i < nE; i += CANT) {
            unsigned int a = i / (unsigned int)C;
            unsigned int c = i - a * (unsigned int)C;
            float s = s1[i];
            if (val[a] && s > HLO)
                rn_push_g(s, b * C + (int)c, (unsigned int)a0 + a);
        }
    }
}

// ---------------------------------------------------------------------------
// K3: per-class exact top-512 (hist threshold + refilter + bitonic sort)
// ---------------------------------------------------------------------------
#define SNT 512

__global__ void __launch_bounds__(SNT)
rn_sort(const float* __restrict__ scores, int B, int A, int C) {
    extern __shared__ unsigned char dyn[];
    unsigned long long* keys  = reinterpret_cast<unsigned long long*>(dyn);  // [KMAX] 16KB
    unsigned int*       fhist = reinterpret_cast<unsigned int*>(dyn);        // alias 32KB

    __shared__ unsigned int hist64[HBINS];
    __shared__ unsigned int chunk[SNT];
    __shared__ unsigned int s_m, s_kk;
    __shared__ int          s_fb;

    const int tid = threadIdx.x;
    const int bc  = blockIdx.x;
    const int b   = bc / C;
    const int c   = bc % C;

    unsigned int n_raw = g_cnt[bc];
    const unsigned long long* __restrict__ gk = g_keys + (size_t)bc * CAPG;

    if (tid == 0) {
        s_fb = (n_raw < KPRE) || (n_raw > CAPG);
        s_m  = 0;
    }
    if (tid < HBINS) hist64[tid] = 0;
    __syncthreads();

    if (!s_fb) {
        for (unsigned int i = tid; i < n_raw; i += SNT) {
            float s = __uint_as_float((unsigned int)(gk[i] >> 32));
            int bin = min((int)((s - HLO) * HSCALE), HBINS - 1);
            atomicAdd(&hist64[bin], 1u);
        }
        __syncthreads();
        if (tid == 0) {
            unsigned int cum = 0;
            int kk = 0;
            for (int k = HBINS - 1; k >= 0; k--) {
                cum += hist64[k];
                if (cum >= KPRE) { kk = k; break; }
            }
            if (cum > KMAX) s_fb = 1;
            s_kk = (unsigned int)kk;
        }
        __syncthreads();
        if (!s_fb) {
            unsigned int kk = s_kk;
            for (unsigned int i = tid; i < n_raw; i += SNT) {
                unsigned long long key = gk[i];
                float s = __uint_as_float((unsigned int)(key >> 32));
                unsigned int bin =
                    (unsigned int)min((int)((s - HLO) * HSCALE), HBINS - 1);
                if (bin >= kk) {
                    unsigned int pos = atomicAdd(&s_m, 1u);
                    if (pos < KMAX) keys[pos] = key;
                }
            }
        }
        __syncthreads();
    }

    if (s_fb) {   // exact strided fallback (never fires for this data)
        for (int i = tid; i < FBINS; i += SNT) fhist[i] = 0;
        if (tid == 0) s_m = 0;
        __syncthreads();
        for (int a = tid; a < A; a += SNT) {
            float s = scores[((size_t)b * A + a) * (size_t)C + c];
            if (g_valid[(size_t)b * A + a] && s > SCORE_THR) {
                int bin = min(max((int)(s * (float)FBINS), 0), FBINS - 1);
                atomicAdd(&fhist[bin], 1u);
            }
        }
        __syncthreads();
        {
            unsigned int cs = 0;
            const int per = FBINS / SNT;
            #pragma unroll
            for (int i = 0; i < FBINS / SNT; i++) cs += fhist[tid * per + i];
            chunk[tid] = cs;
        }
        __syncthreads();
        if (tid == 0) {
            const int per = FBINS / SNT;
            unsigned int cum = 0;
            int cc;
            for (cc = SNT - 1; cc >= 0; cc--) {
                if (cum + chunk[cc] >= KPRE) break;
                cum += chunk[cc];
            }
            int kk = 0;
            if (cc >= 0) {
                int bs = cc * per;
                for (int bb = bs + per - 1; bb >= bs; bb--) {
                    cum += fhist[bb];
                    if (cum >= KPRE) { kk = bb; break; }
                }
            }
            while (cum > KMAX && kk < FBINS - 1) { cum -= fhist[kk]; kk++; }
            s_kk = (unsigned int)kk;
        }
        __syncthreads();
        unsigned int kk = s_kk;
        __syncthreads();   // fhist reads done before keys (alias) writes
        for (int a = tid; a < A; a += SNT) {
            float s = scores[((size_t)b * A + a) * (size_t)C + c];
            if (g_valid[(size_t)b * A + a] && s > SCORE_THR) {
                unsigned int bin =
                    (unsigned int)min((int)(s * (float)FBINS), FBINS - 1);
                if (bin >= kk) {
                    unsigned int pos = atomicAdd(&s_m, 1u);
                    if (pos < KMAX)
                        keys[pos] =
                            ((unsigned long long)__float_as_uint(s) << 32) |
                            (unsigned long long)(0xFFFFFFFFu - (unsigned int)a);
                }
            }
        }
        __syncthreads();
    }

    unsigned int m = min(s_m, (unsigned int)KMAX);
    const int NSORT = (m <= 1024u) ? 1024 : 2048;
    for (int i = tid; i < NSORT; i += SNT)
        if (i >= (int)m) keys[i] = 0ULL;
    __syncthreads();

    for (int k = 2; k <= NSORT; k <<= 1) {
        for (int j = k >> 1; j > 0; j >>= 1) {
            for (int i = tid; i < NSORT; i += SNT) {
                int ixj = i ^ j;
                if (ixj > i) {
                    unsigned long long x = keys[i];
                    unsigned long long y = keys[ixj];
                    bool desc = ((i & k) == 0);
                    if (desc ? (x < y) : (x > y)) { keys[i] = y; keys[ixj] = x; }
                }
            }
            __syncthreads();
        }
    }

    g_top[(size_t)bc * 512 + tid] = keys[tid];   // SNT==512 sorted top keys
}

// ---------------------------------------------------------------------------
// K4: per-class IoU suppression bitmask -> global (ballot-based)
// ---------------------------------------------------------------------------
__global__ void __launch_bounds__(512)
rn_iou(int B, int A, int C) {
    __shared__ float4 cbox[KPRE];
    __shared__ float  carea[KPRE];

    const int tid = threadIdx.x;
    const int bc  = blockIdx.x;
    const int b   = bc / C;

    if (tid < KPRE) {
        unsigned long long key = g_top[(size_t)bc * 512 + tid];
        float s = __uint_as_float((unsigned int)(key >> 32));
        unsigned int aidx = 0xFFFFFFFFu - (unsigned int)(key & 0xFFFFFFFFull);
        float4 bx = make_float4(0.0f, 0.0f, 0.0f, 0.0f);
        if (s > SCORE_THR)
            bx = reinterpret_cast<const float4*>(g_boxes)[(size_t)b * A + aidx];
        cbox[tid]  = bx;
        carea[tid] = (bx.z - bx.x) * (bx.w - bx.y);
    }
    __syncthreads();

    const int lane = tid & 31;
    const int wrp  = tid >> 5;
    unsigned int* __restrict__ om = g_ioum + (size_t)bc * KPRE * 16;

    for (int g = wrp; g * 8 < KPRE; g += 16) {
        int i0 = g * 8;
        float4 bi[8];
        float  ai[8];
        #pragma unroll
        for (int r = 0; r < 8; r++) {
            int i = i0 + r;
            if (i < KPRE) { bi[r] = cbox[i]; ai[r] = carea[i]; }
            else { bi[r] = make_float4(0, 0, 0, 0); ai[r] = 0.0f; }
        }
        for (int ch = 0; ch < 16; ch++) {
            int j = ch * 32 + lane;
            float4 bj = (j < KPRE) ? cbox[j] : make_float4(0, 0, 0, 0);
            float  aj = (j < KPRE) ? carea[j] : 0.0f;
            #pragma unroll
            for (int r = 0; r < 8; r++) {
                int i = i0 + r;
                float lx = fmaxf(bi[r].x, bj.x);
                float ly = fmaxf(bi[r].y, bj.y);
                float rx = fminf(bi[r].z, bj.z);
                float ry = fminf(bi[r].w, bj.w);
                float iw = fmaxf(rx - lx, 0.0f);
                float ih = fmaxf(ry - ly, 0.0f);
                float inter = iw * ih;
                float iou = inter / fmaxf(ai[r] + aj - inter, 1e-9f);
                bool pred = (j < KPRE) && (j > i) && (iou > NMS_THR);
                unsigned int mask = __ballot_sync(0xFFFFFFFFu, pred);
                if (lane == r && i < KPRE) om[i * 16 + ch] = mask;
            }
        }
    }
}

// ---------------------------------------------------------------------------
// K5: serial-semantics NMS scan + ranked output
// ---------------------------------------------------------------------------
__global__ void __launch_bounds__(512)
rn_scan(float* __restrict__ out, int B, int A, int C) {
    __shared__ unsigned int ioum[KPRE * 16];   // 32000 B
    __shared__ float4       cbox[KPRE];        // 8000 B
    __shared__ float        cscore[KPRE];
    __shared__ unsigned int keep0[16], keepw[16], pref[16];
    __shared__ unsigned int s_nkeep;

    const int tid = threadIdx.x;
    const int bc  = blockIdx.x;
    const int b   = bc / C;

    if (tid < 16) keep0[tid] = 0;
    // load mask slab (coalesced uint4)
    {
        const uint4* __restrict__ src =
            reinterpret_cast<const uint4*>(g_ioum + (size_t)bc * KPRE * 16);
        uint4* dst = reinterpret_cast<uint4*>(ioum);
        for (int i = tid; i < KPRE * 4; i += 512) dst[i] = src[i];
    }
    if (tid < KPRE) {
        unsigned long long key = g_top[(size_t)bc * 512 + tid];
        float s = __uint_as_float((unsigned int)(key >> 32));
        unsigned int aidx = 0xFFFFFFFFu - (unsigned int)(key & 0xFFFFFFFFull);
        bool cv = (s > SCORE_THR);
        cscore[tid] = s;
        float4 bx = make_float4(0.0f, 0.0f, 0.0f, 0.0f);
        if (cv) bx = reinterpret_cast<const float4*>(g_boxes)[(size_t)b * A + aidx];
        cbox[tid] = bx;
        if (cv) atomicOr(&keep0[tid >> 5], 1u << (tid & 31));
    }
    __syncthreads();

    if (tid < 16) {
        unsigned int kw = keep0[tid];
        int kept = 0;
        for (int w = 0; w < 16 && kept < MAXDET; w++) {
            unsigned int p = 0;
            while (true) {
                unsigned int cur = __shfl_sync(0xFFFFu, kw, w);
                unsigned int rem = (p < 32u)
                    ? (cur & (p ? (0xFFFFFFFFu << p) : 0xFFFFFFFFu)) : 0u;
                if (!rem) break;
                int bit = __ffs(rem) - 1;
                int i = w * 32 + bit;
                kw &= ~ioum[i * 16 + tid];
                kept++;
                if (kept >= MAXDET) break;
                p = (unsigned int)bit + 1u;
            }
        }
        keepw[tid] = kw;
        unsigned int pc = __popc(kw);
        unsigned int scan = pc;
        #pragma unroll
        for (int o = 1; o < 16; o <<= 1) {
            unsigned int v = __shfl_up_sync(0xFFFFu, scan, o);
            if (tid >= o) scan += v;
        }
        pref[tid] = scan - pc;
        if (tid == 15) s_nkeep = scan;
    }
    __syncthreads();

    float* outp = out + (size_t)bc * MAXDET * 5;
    if (tid < KPRE) {
        unsigned int kw = keepw[tid >> 5];
        if ((kw >> (tid & 31)) & 1u) {
            unsigned int rank = pref[tid >> 5] + __popc(kw & ((1u << (tid & 31)) - 1u));
            if (rank < MAXDET) {
                float4 bx = cbox[tid];
                outp[rank * 5 + 0] = bx.x;
                outp[rank * 5 + 1] = bx.y;
                outp[rank * 5 + 2] = bx.z;
                outp[rank * 5 + 3] = bx.w;
                outp[rank * 5 + 4] = cscore[tid];
            }
        }
    }
    unsigned int nk = min(s_nkeep, (unsigned int)MAXDET);
    for (int r = (int)nk + tid; r < MAXDET; r += 512) {
        outp[r * 5 + 0] = 0.0f;
        outp[r * 5 + 1] = 0.0f;
        outp[r * 5 + 2] = 0.0f;
        outp[r * 5 + 3] = 0.0f;
        outp[r * 5 + 4] = -1.0f;
    }
}

// ---------------------------------------------------------------------------
// host launch
// ---------------------------------------------------------------------------
extern "C" void kernel_launch(void* const* d_in, const int* in_sizes, int n_in,
                              void* d_out, int out_size) {
    const float* deltas  = (const float*)d_in[0];
    const float* scores  = (const float*)d_in[1];
    const float* anchors = (const float*)d_in[2];
    const int*   imh     = (const int*)d_in[3];
    const int*   imw     = (const int*)d_in[4];

    long long nd = in_sizes[0];
    long long ns = in_sizes[1];
    int C  = (int)(ns * 4 / nd);
    int BC = out_size / (MAXDET * 5);
    int B  = BC / C;
    int A  = (int)(nd / (4LL * B));

    float* out = (float*)d_out;

    int n = B * A;
    rn_decode<<<(n + 255) / 256, 256>>>(deltas, anchors, imh, imw, B, A);

    dim3 cg((A + CA - 1) / CA, B);
    rn_collect<<<cg, CANT>>>(scores, B, A, C);

    rn_sort<<<BC, SNT, 32768>>>(scores, B, A, C);
    rn_iou<<<BC, 512>>>(B, A, C);
    rn_scan<<<BC, 512>>>(out, B, A, C);
}

// round 7
// speedup vs baseline: 3.7848x; 1.2792x over previous
#include <cuda_runtime.h>
#include <stdint.h>

#define KPRE       500
#define MAXDET     300
#define SCORE_THR  0.05f
#define NMS_THR    0.5f
#define MIN_SIZE   0.01f
#define BBOX_CLAMP 4.135166556742356f   // log(1000/16)

#define HLO        0.99f
#define HBINS      64
#define HSCALE     6400.0f               // HBINS / (1 - HLO)
#define CAPG       16384
#define KMAX       2048
#define FBINS      8192

#define BMAX   2
#define AMAX   131072
#define CMAX   96
#define BCMAX  192

__device__ float              g_boxes[(size_t)BMAX * AMAX * 4];
__device__ unsigned char      g_valid[(size_t)BMAX * AMAX];
__device__ unsigned long long g_keys[(size_t)BCMAX * CAPG];
__device__ unsigned int       g_cnt[BCMAX];
__device__ unsigned long long g_top[(size_t)BCMAX * 512];
__device__ unsigned int       g_ioum[(size_t)BCMAX * KPRE * 16];

// ---------------------------------------------------------------------------
// K1: decode + clamp + valid mask; zero per-class counters
// ---------------------------------------------------------------------------
__global__ void rn_decode(const float* __restrict__ deltas,
                          const float* __restrict__ anchors,
                          const int* __restrict__ imh,
                          const int* __restrict__ imw,
                          int B, int A) {
    int i = blockIdx.x * blockDim.x + threadIdx.x;
    if (i < BCMAX) g_cnt[i] = 0;
    if (i >= B * A) return;
    float W = (float)imw[0];
    float H = (float)imh[0];
    float4 an = reinterpret_cast<const float4*>(anchors)[i];
    float4 dt = reinterpret_cast<const float4*>(deltas)[i];
    float aw  = an.z - an.x;
    float ah  = an.w - an.y;
    float acx = an.x + 0.5f * aw;
    float acy = an.y + 0.5f * ah;
    float dw  = fminf(dt.z, BBOX_CLAMP);
    float dh  = fminf(dt.w, BBOX_CLAMP);
    float pcx = dt.x * aw + acx;
    float pcy = dt.y * ah + acy;
    float pw  = expf(dw) * aw;
    float ph  = expf(dh) * ah;
    float x1 = fminf(fmaxf(pcx - 0.5f * pw, 0.0f), W);
    float y1 = fminf(fmaxf(pcy - 0.5f * ph, 0.0f), H);
    float x2 = fminf(fmaxf(pcx + 0.5f * pw, 0.0f), W);
    float y2 = fminf(fmaxf(pcy + 0.5f * ph, 0.0f), H);
    reinterpret_cast<float4*>(g_boxes)[i] = make_float4(x1, y1, x2, y2);
    g_valid[i] = (((x2 - x1) >= MIN_SIZE) && ((y2 - y1) >= MIN_SIZE)) ? 1 : 0;
}

// ---------------------------------------------------------------------------
// K2: single coalesced pass; push (valid & s > HLO) into class buffers
// ---------------------------------------------------------------------------
#define CA   256     // anchors per block
#define CANT 256

__device__ __forceinline__ void rn_push_g(float s, int bc, unsigned int a) {
    unsigned int pos = atomicAdd(&g_cnt[bc], 1u);
    if (pos < CAPG)
        g_keys[(size_t)bc * CAPG + pos] =
            ((unsigned long long)__float_as_uint(s) << 32) |
            (unsigned long long)(0xFFFFFFFFu - a);
}

__global__ void __launch_bounds__(CANT)
rn_collect(const float* __restrict__ scores, int B, int A, int C) {
    int b   = blockIdx.y;
    int a0  = blockIdx.x * CA;
    int na  = min(CA, A - a0);
    int tid = threadIdx.x;
    const unsigned char* __restrict__ val = g_valid + (size_t)b * A + a0;

    if ((C & 3) == 0) {
        unsigned int C4 = (unsigned int)C >> 2;
        const float4* __restrict__ s4 =
            reinterpret_cast<const float4*>(scores + ((size_t)b * A + a0) * C);
        unsigned int n4 = (unsigned int)na * C4;

        auto proc = [&](float4 v, unsigned int i) {
            if (!(v.x > HLO) && !(v.y > HLO) && !(v.z > HLO) && !(v.w > HLO))
                return;
            unsigned int a  = i / C4;
            unsigned int c4 = (i - a * C4) << 2;
            if (!val[a]) return;
            int bc = b * C + (int)c4;
            unsigned int ag = (unsigned int)a0 + a;
            if (v.x > HLO) rn_push_g(v.x, bc + 0, ag);
            if (v.y > HLO) rn_push_g(v.y, bc + 1, ag);
            if (v.z > HLO) rn_push_g(v.z, bc + 2, ag);
            if (v.w > HLO) rn_push_g(v.w, bc + 3, ag);
        };

        unsigned int i = (unsigned int)tid;
        for (; i + 3u * CANT < n4; i += 4u * CANT) {
            float4 v0 = __ldcs(&s4[i]);
            float4 v1 = __ldcs(&s4[i + CANT]);
            float4 v2 = __ldcs(&s4[i + 2u * CANT]);
            float4 v3 = __ldcs(&s4[i + 3u * CANT]);
            proc(v0, i);
            proc(v1, i + CANT);
            proc(v2, i + 2u * CANT);
            proc(v3, i + 3u * CANT);
        }
        for (; i < n4; i += CANT) proc(__ldcs(&s4[i]), i);
    } else {
        const float* __restrict__ s1 = scores + ((size_t)b * A + a0) * C;
        unsigned int nE = (unsigned int)na * (unsigned int)C;
        for (unsigned int i = (unsigned int)tid; i < nE; i += CANT) {
            unsigned int a = i / (unsigned int)C;
            unsigned int c = i - a * (unsigned int)C;
            float s = s1[i];
            if (val[a] && s > HLO)
                rn_push_g(s, b * C + (int)c, (unsigned int)a0 + a);
        }
    }
}

// ---------------------------------------------------------------------------
// K3: per-class exact top-512 (hist threshold + refilter + bitonic sort)
// ---------------------------------------------------------------------------
#define SNT 512

__global__ void __launch_bounds__(SNT)
rn_sort(const float* __restrict__ scores, int B, int A, int C) {
    extern __shared__ unsigned char dyn[];
    unsigned long long* keys  = reinterpret_cast<unsigned long long*>(dyn);  // [KMAX] 16KB
    unsigned int*       fhist = reinterpret_cast<unsigned int*>(dyn);        // alias 32KB

    __shared__ unsigned int hist64[HBINS];
    __shared__ unsigned int chunk[SNT];
    __shared__ unsigned int s_m, s_kk;
    __shared__ int          s_fb;

    const int tid = threadIdx.x;
    const int bc  = blockIdx.x;
    const int b   = bc / C;
    const int c   = bc % C;

    unsigned int n_raw = g_cnt[bc];
    const unsigned long long* __restrict__ gk = g_keys + (size_t)bc * CAPG;

    if (tid == 0) {
        s_fb = (n_raw < KPRE) || (n_raw > CAPG);
        s_m  = 0;
    }
    if (tid < HBINS) hist64[tid] = 0;
    __syncthreads();

    if (!s_fb) {
        for (unsigned int i = tid; i < n_raw; i += SNT) {
            float s = __uint_as_float((unsigned int)(gk[i] >> 32));
            int bin = min((int)((s - HLO) * HSCALE), HBINS - 1);
            atomicAdd(&hist64[bin], 1u);
        }
        __syncthreads();
        if (tid == 0) {
            unsigned int cum = 0;
            int kk = 0;
            for (int k = HBINS - 1; k >= 0; k--) {
                cum += hist64[k];
                if (cum >= KPRE) { kk = k; break; }
            }
            if (cum > KMAX) s_fb = 1;
            s_kk = (unsigned int)kk;
        }
        __syncthreads();
        if (!s_fb) {
            unsigned int kk = s_kk;
            for (unsigned int i = tid; i < n_raw; i += SNT) {
                unsigned long long key = gk[i];
                float s = __uint_as_float((unsigned int)(key >> 32));
                unsigned int bin =
                    (unsigned int)min((int)((s - HLO) * HSCALE), HBINS - 1);
                if (bin >= kk) {
                    unsigned int pos = atomicAdd(&s_m, 1u);
                    if (pos < KMAX) keys[pos] = key;
                }
            }
        }
        __syncthreads();
    }

    if (s_fb) {   // exact strided fallback (never fires for this data)
        for (int i = tid; i < FBINS; i += SNT) fhist[i] = 0;
        if (tid == 0) s_m = 0;
        __syncthreads();
        for (int a = tid; a < A; a += SNT) {
            float s = scores[((size_t)b * A + a) * (size_t)C + c];
            if (g_valid[(size_t)b * A + a] && s > SCORE_THR) {
                int bin = min(max((int)(s * (float)FBINS), 0), FBINS - 1);
                atomicAdd(&fhist[bin], 1u);
            }
        }
        __syncthreads();
        {
            unsigned int cs = 0;
            const int per = FBINS / SNT;
            #pragma unroll
            for (int i = 0; i < FBINS / SNT; i++) cs += fhist[tid * per + i];
            chunk[tid] = cs;
        }
        __syncthreads();
        if (tid == 0) {
            const int per = FBINS / SNT;
            unsigned int cum = 0;
            int cc;
            for (cc = SNT - 1; cc >= 0; cc--) {
                if (cum + chunk[cc] >= KPRE) break;
                cum += chunk[cc];
            }
            int kk = 0;
            if (cc >= 0) {
                int bs = cc * per;
                for (int bb = bs + per - 1; bb >= bs; bb--) {
                    cum += fhist[bb];
                    if (cum >= KPRE) { kk = bb; break; }
                }
            }
            while (cum > KMAX && kk < FBINS - 1) { cum -= fhist[kk]; kk++; }
            s_kk = (unsigned int)kk;
        }
        __syncthreads();
        unsigned int kk = s_kk;
        __syncthreads();   // fhist reads done before keys (alias) writes
        for (int a = tid; a < A; a += SNT) {
            float s = scores[((size_t)b * A + a) * (size_t)C + c];
            if (g_valid[(size_t)b * A + a] && s > SCORE_THR) {
                unsigned int bin =
                    (unsigned int)min((int)(s * (float)FBINS), FBINS - 1);
                if (bin >= kk) {
                    unsigned int pos = atomicAdd(&s_m, 1u);
                    if (pos < KMAX)
                        keys[pos] =
                            ((unsigned long long)__float_as_uint(s) << 32) |
                            (unsigned long long)(0xFFFFFFFFu - (unsigned int)a);
                }
            }
        }
        __syncthreads();
    }

    unsigned int m = min(s_m, (unsigned int)KMAX);
    const int NSORT = (m <= 1024u) ? 1024 : 2048;
    for (int i = tid; i < NSORT; i += SNT)
        if (i >= (int)m) keys[i] = 0ULL;
    __syncthreads();

    for (int k = 2; k <= NSORT; k <<= 1) {
        for (int j = k >> 1; j > 0; j >>= 1) {
            for (int i = tid; i < NSORT; i += SNT) {
                int ixj = i ^ j;
                if (ixj > i) {
                    unsigned long long x = keys[i];
                    unsigned long long y = keys[ixj];
                    bool desc = ((i & k) == 0);
                    if (desc ? (x < y) : (x > y)) { keys[i] = y; keys[ixj] = x; }
                }
            }
            __syncthreads();
        }
    }

    g_top[(size_t)bc * 512 + tid] = keys[tid];   // SNT==512 sorted top keys
}

// ---------------------------------------------------------------------------
// K4: per-class IoU suppression bitmask (lane-private words, no ballots)
// grid=(BC, 4), block=128: warp w owns row-group g = blockIdx.y*4+w (32 rows)
// ---------------------------------------------------------------------------
__global__ void __launch_bounds__(128)
rn_iou(int B, int A, int C) {
    __shared__ float4 cbox[512];
    __shared__ float  carea[512];

    const int tid = threadIdx.x;
    const int bc  = blockIdx.x;
    const int b   = bc / C;

    for (int idx = tid; idx < 512; idx += 128) {
        float4 bx = make_float4(0.0f, 0.0f, 0.0f, 0.0f);
        if (idx < KPRE) {
            unsigned long long key = g_top[(size_t)bc * 512 + idx];
            float s = __uint_as_float((unsigned int)(key >> 32));
            unsigned int aidx = 0xFFFFFFFFu - (unsigned int)(key & 0xFFFFFFFFull);
            if (s > SCORE_THR)
                bx = reinterpret_cast<const float4*>(g_boxes)[(size_t)b * A + aidx];
        }
        cbox[idx]  = bx;
        carea[idx] = (bx.z - bx.x) * (bx.w - bx.y);
    }
    __syncthreads();

    const int lane = tid & 31;
    const int g    = blockIdx.y * 4 + (tid >> 5);   // row group 0..15
    const int i    = g * 32 + lane;
    const bool vi  = (i < KPRE);

    float4 bi = vi ? cbox[i] : make_float4(0, 0, 0, 0);
    float  ai = vi ? carea[i] : 0.0f;

    unsigned int* __restrict__ om = g_ioum + (size_t)bc * KPRE * 16;

    for (int ch = 0; ch < 16; ch++) {
        unsigned int m = 0;
        if (ch >= g) {                 // ch < g: j <= 32ch+31 < i -> all zero
            int jbase = ch * 32;
            #pragma unroll 8
            for (int jj = 0; jj < 32; jj++) {
                int j = jbase + jj;    // broadcast LDS across lanes
                float4 bj = cbox[j];
                float  aj = carea[j];
                float lx = fmaxf(bi.x, bj.x);
                float ly = fmaxf(bi.y, bj.y);
                float rx = fminf(bi.z, bj.z);
                float ry = fminf(bi.w, bj.w);
                float iw = fmaxf(rx - lx, 0.0f);
                float ih = fmaxf(ry - ly, 0.0f);
                float inter = iw * ih;
                float iou = inter / fmaxf(ai + aj - inter, 1e-9f);
                bool pred = (j > i) && (iou > NMS_THR);   // j>=KPRE: area 0 -> iou 0
                m |= ((unsigned int)pred) << jj;
            }
        }
        if (vi) om[i * 16 + ch] = m;
    }
}

// ---------------------------------------------------------------------------
// K5: serial-semantics NMS scan + ranked output
// ---------------------------------------------------------------------------
__global__ void __launch_bounds__(512)
rn_scan(float* __restrict__ out, int B, int A, int C) {
    __shared__ unsigned int ioum[KPRE * 16];   // 32000 B
    __shared__ float4       cbox[KPRE];        // 8000 B
    __shared__ float        cscore[KPRE];
    __shared__ unsigned int keep0[16], keepw[16], pref[16];
    __shared__ unsigned int s_nkeep;

    const int tid = threadIdx.x;
    const int bc  = blockIdx.x;
    const int b   = bc / C;

    if (tid < 16) keep0[tid] = 0;
    {
        const uint4* __restrict__ src =
            reinterpret_cast<const uint4*>(g_ioum + (size_t)bc * KPRE * 16);
        uint4* dst = reinterpret_cast<uint4*>(ioum);
        for (int i = tid; i < KPRE * 4; i += 512) dst[i] = src[i];
    }
    if (tid < KPRE) {
        unsigned long long key = g_top[(size_t)bc * 512 + tid];
        float s = __uint_as_float((unsigned int)(key >> 32));
        unsigned int aidx = 0xFFFFFFFFu - (unsigned int)(key & 0xFFFFFFFFull);
        bool cv = (s > SCORE_THR);
        cscore[tid] = s;
        float4 bx = make_float4(0.0f, 0.0f, 0.0f, 0.0f);
        if (cv) bx = reinterpret_cast<const float4*>(g_boxes)[(size_t)b * A + aidx];
        cbox[tid] = bx;
        if (cv) atomicOr(&keep0[tid >> 5], 1u << (tid & 31));
    }
    __syncthreads();

    if (tid < 16) {
        unsigned int kw = keep0[tid];
        int kept = 0;
        for (int w = 0; w < 16 && kept < MAXDET; w++) {
            unsigned int p = 0;
            while (true) {
                unsigned int cur = __shfl_sync(0xFFFFu, kw, w);
                unsigned int rem = (p < 32u)
                    ? (cur & (p ? (0xFFFFFFFFu << p) : 0xFFFFFFFFu)) : 0u;
                if (!rem) break;
                int bit = __ffs(rem) - 1;
                int i = w * 32 + bit;
                kw &= ~ioum[i * 16 + tid];
                kept++;
                if (kept >= MAXDET) break;
                p = (unsigned int)bit + 1u;
            }
        }
        keepw[tid] = kw;
        unsigned int pc = __popc(kw);
        unsigned int scan = pc;
        #pragma unroll
        for (int o = 1; o < 16; o <<= 1) {
            unsigned int v = __shfl_up_sync(0xFFFFu, scan, o);
            if (tid >= o) scan += v;
        }
        pref[tid] = scan - pc;
        if (tid == 15) s_nkeep = scan;
    }
    __syncthreads();

    float* outp = out + (size_t)bc * MAXDET * 5;
    if (tid < KPRE) {
        unsigned int kw = keepw[tid >> 5];
        if ((kw >> (tid & 31)) & 1u) {
            unsigned int rank = pref[tid >> 5] + __popc(kw & ((1u << (tid & 31)) - 1u));
            if (rank < MAXDET) {
                float4 bx = cbox[tid];
                outp[rank * 5 + 0] = bx.x;
                outp[rank * 5 + 1] = bx.y;
                outp[rank * 5 + 2] = bx.z;
                outp[rank * 5 + 3] = bx.w;
                outp[rank * 5 + 4] = cscore[tid];
            }
        }
    }
    unsigned int nk = min(s_nkeep, (unsigned int)MAXDET);
    for (int r = (int)nk + tid; r < MAXDET; r += 512) {
        outp[r * 5 + 0] = 0.0f;
        outp[r * 5 + 1] = 0.0f;
        outp[r * 5 + 2] = 0.0f;
        outp[r * 5 + 3] = 0.0f;
        outp[r * 5 + 4] = -1.0f;
    }
}

// ---------------------------------------------------------------------------
// host launch
// ---------------------------------------------------------------------------
extern "C" void kernel_launch(void* const* d_in, const int* in_sizes, int n_in,
                              void* d_out, int out_size) {
    const float* deltas  = (const float*)d_in[0];
    const float* scores  = (const float*)d_in[1];
    const float* anchors = (const float*)d_in[2];
    const int*   imh     = (const int*)d_in[3];
    const int*   imw     = (const int*)d_in[4];

    long long nd = in_sizes[0];
    long long ns = in_sizes[1];
    int C  = (int)(ns * 4 / nd);
    int BC = out_size / (MAXDET * 5);
    int B  = BC / C;
    int A  = (int)(nd / (4LL * B));

    float* out = (float*)d_out;

    int n = B * A;
    rn_decode<<<(n + 255) / 256, 256>>>(deltas, anchors, imh, imw, B, A);

    dim3 cg((A + CA - 1) / CA, B);
    rn_collect<<<cg, CANT>>>(scores, B, A, C);

    rn_sort<<<BC, SNT, 32768>>>(scores, B, A, C);
    rn_iou<<<dim3(BC, 4), 128>>>(B, A, C);
    rn_scan<<<BC, 512>>>(out, B, A, C);
}

// round 8
// speedup vs baseline: 5.8023x; 1.5330x over previous
#include <cuda_runtime.h>
#include <stdint.h>

#define KPRE       500
#define MAXDET     300
#define SCORE_THR  0.05f
#define NMS_THR    0.5f
#define MIN_SIZE   0.01f
#define BBOX_CLAMP 4.135166556742356f   // log(1000/16)

#define HLO        0.99f
#define HBINS      64
#define HSCALE     6400.0f               // HBINS / (1 - HLO)
#define CAPG       16384
#define KMAX       2048
#define FBINS      8192

#define BMAX   2
#define AMAX   131072
#define CMAX   96
#define BCMAX  192

__device__ float              g_boxes[(size_t)BMAX * AMAX * 4];
__device__ unsigned char      g_valid[(size_t)BMAX * AMAX];
__device__ unsigned long long g_keys[(size_t)BCMAX * CAPG];
__device__ unsigned int       g_cnt[BCMAX];
__device__ unsigned long long g_top[(size_t)BCMAX * 512];
__device__ float4             g_cbox[(size_t)BCMAX * 512];
__device__ float              g_carea[(size_t)BCMAX * 512];
__device__ unsigned int       g_ioum[(size_t)BCMAX * KPRE * 16];

// ---------------------------------------------------------------------------
// K1: decode + clamp + valid mask; zero per-class counters
// ---------------------------------------------------------------------------
__global__ void rn_decode(const float* __restrict__ deltas,
                          const float* __restrict__ anchors,
                          const int* __restrict__ imh,
                          const int* __restrict__ imw,
                          int B, int A) {
    int i = blockIdx.x * blockDim.x + threadIdx.x;
    if (i < BCMAX) g_cnt[i] = 0;
    if (i >= B * A) return;
    float W = (float)imw[0];
    float H = (float)imh[0];
    float4 an = reinterpret_cast<const float4*>(anchors)[i];
    float4 dt = reinterpret_cast<const float4*>(deltas)[i];
    float aw  = an.z - an.x;
    float ah  = an.w - an.y;
    float acx = an.x + 0.5f * aw;
    float acy = an.y + 0.5f * ah;
    float dw  = fminf(dt.z, BBOX_CLAMP);
    float dh  = fminf(dt.w, BBOX_CLAMP);
    float pcx = dt.x * aw + acx;
    float pcy = dt.y * ah + acy;
    float pw  = expf(dw) * aw;
    float ph  = expf(dh) * ah;
    float x1 = fminf(fmaxf(pcx - 0.5f * pw, 0.0f), W);
    float y1 = fminf(fmaxf(pcy - 0.5f * ph, 0.0f), H);
    float x2 = fminf(fmaxf(pcx + 0.5f * pw, 0.0f), W);
    float y2 = fminf(fmaxf(pcy + 0.5f * ph, 0.0f), H);
    reinterpret_cast<float4*>(g_boxes)[i] = make_float4(x1, y1, x2, y2);
    g_valid[i] = (((x2 - x1) >= MIN_SIZE) && ((y2 - y1) >= MIN_SIZE)) ? 1 : 0;
}

// ---------------------------------------------------------------------------
// K2: single coalesced pass; push (valid & s > HLO) into class buffers
// ---------------------------------------------------------------------------
#define CA   256     // anchors per block
#define CANT 256

__device__ __forceinline__ void rn_push_g(float s, int bc, unsigned int a) {
    unsigned int pos = atomicAdd(&g_cnt[bc], 1u);
    if (pos < CAPG)
        g_keys[(size_t)bc * CAPG + pos] =
            ((unsigned long long)__float_as_uint(s) << 32) |
            (unsigned long long)(0xFFFFFFFFu - a);
}

__global__ void __launch_bounds__(CANT)
rn_collect(const float* __restrict__ scores, int B, int A, int C) {
    int b   = blockIdx.y;
    int a0  = blockIdx.x * CA;
    int na  = min(CA, A - a0);
    int tid = threadIdx.x;
    const unsigned char* __restrict__ val = g_valid + (size_t)b * A + a0;

    if ((C & 3) == 0) {
        unsigned int C4 = (unsigned int)C >> 2;
        const float4* __restrict__ s4 =
            reinterpret_cast<const float4*>(scores + ((size_t)b * A + a0) * C);
        unsigned int n4 = (unsigned int)na * C4;

        auto proc = [&](float4 v, unsigned int i) {
            if (!(v.x > HLO) && !(v.y > HLO) && !(v.z > HLO) && !(v.w > HLO))
                return;
            unsigned int a  = i / C4;
            unsigned int c4 = (i - a * C4) << 2;
            if (!val[a]) return;
            int bc = b * C + (int)c4;
            unsigned int ag = (unsigned int)a0 + a;
            if (v.x > HLO) rn_push_g(v.x, bc + 0, ag);
            if (v.y > HLO) rn_push_g(v.y, bc + 1, ag);
            if (v.z > HLO) rn_push_g(v.z, bc + 2, ag);
            if (v.w > HLO) rn_push_g(v.w, bc + 3, ag);
        };

        unsigned int i = (unsigned int)tid;
        for (; i + 3u * CANT < n4; i += 4u * CANT) {
            float4 v0 = __ldcs(&s4[i]);
            float4 v1 = __ldcs(&s4[i + CANT]);
            float4 v2 = __ldcs(&s4[i + 2u * CANT]);
            float4 v3 = __ldcs(&s4[i + 3u * CANT]);
            proc(v0, i);
            proc(v1, i + CANT);
            proc(v2, i + 2u * CANT);
            proc(v3, i + 3u * CANT);
        }
        for (; i < n4; i += CANT) proc(__ldcs(&s4[i]), i);
    } else {
        const float* __restrict__ s1 = scores + ((size_t)b * A + a0) * C;
        unsigned int nE = (unsigned int)na * (unsigned int)C;
        for (unsigned int i = (unsigned int)tid; i < nE; i += CANT) {
            unsigned int a = i / (unsigned int)C;
            unsigned int c = i - a * (unsigned int)C;
            float s = s1[i];
            if (val[a] && s > HLO)
                rn_push_g(s, b * C + (int)c, (unsigned int)a0 + a);
        }
    }
}

// ---------------------------------------------------------------------------
// K3: per-class exact top-512 (hist threshold + refilter + bitonic sort)
//     epilogue gathers boxes/areas into g_cbox/g_carea
// ---------------------------------------------------------------------------
#define SNT 512

__global__ void __launch_bounds__(SNT)
rn_sort(const float* __restrict__ scores, int B, int A, int C) {
    extern __shared__ unsigned char dyn[];
    unsigned long long* keys  = reinterpret_cast<unsigned long long*>(dyn);  // [KMAX] 16KB
    unsigned int*       fhist = reinterpret_cast<unsigned int*>(dyn);        // alias 32KB

    __shared__ unsigned int hist64[HBINS];
    __shared__ unsigned int chunk[SNT];
    __shared__ unsigned int s_m, s_kk;
    __shared__ int          s_fb;

    const int tid = threadIdx.x;
    const int bc  = blockIdx.x;
    const int b   = bc / C;
    const int c   = bc % C;

    unsigned int n_raw = g_cnt[bc];
    const unsigned long long* __restrict__ gk = g_keys + (size_t)bc * CAPG;

    if (tid == 0) {
        s_fb = (n_raw < KPRE) || (n_raw > CAPG);
        s_m  = 0;
    }
    if (tid < HBINS) hist64[tid] = 0;
    __syncthreads();

    if (!s_fb) {
        for (unsigned int i = tid; i < n_raw; i += SNT) {
            float s = __uint_as_float((unsigned int)(gk[i] >> 32));
            int bin = min((int)((s - HLO) * HSCALE), HBINS - 1);
            atomicAdd(&hist64[bin], 1u);
        }
        __syncthreads();
        if (tid == 0) {
            unsigned int cum = 0;
            int kk = 0;
            for (int k = HBINS - 1; k >= 0; k--) {
                cum += hist64[k];
                if (cum >= KPRE) { kk = k; break; }
            }
            if (cum > KMAX) s_fb = 1;
            s_kk = (unsigned int)kk;
        }
        __syncthreads();
        if (!s_fb) {
            unsigned int kk = s_kk;
            for (unsigned int i = tid; i < n_raw; i += SNT) {
                unsigned long long key = gk[i];
                float s = __uint_as_float((unsigned int)(key >> 32));
                unsigned int bin =
                    (unsigned int)min((int)((s - HLO) * HSCALE), HBINS - 1);
                if (bin >= kk) {
                    unsigned int pos = atomicAdd(&s_m, 1u);
                    if (pos < KMAX) keys[pos] = key;
                }
            }
        }
        __syncthreads();
    }

    if (s_fb) {   // exact strided fallback (never fires for this data)
        for (int i = tid; i < FBINS; i += SNT) fhist[i] = 0;
        if (tid == 0) s_m = 0;
        __syncthreads();
        for (int a = tid; a < A; a += SNT) {
            float s = scores[((size_t)b * A + a) * (size_t)C + c];
            if (g_valid[(size_t)b * A + a] && s > SCORE_THR) {
                int bin = min(max((int)(s * (float)FBINS), 0), FBINS - 1);
                atomicAdd(&fhist[bin], 1u);
            }
        }
        __syncthreads();
        {
            unsigned int cs = 0;
            const int per = FBINS / SNT;
            #pragma unroll
            for (int i = 0; i < FBINS / SNT; i++) cs += fhist[tid * per + i];
            chunk[tid] = cs;
        }
        __syncthreads();
        if (tid == 0) {
            const int per = FBINS / SNT;
            unsigned int cum = 0;
            int cc;
            for (cc = SNT - 1; cc >= 0; cc--) {
                if (cum + chunk[cc] >= KPRE) break;
                cum += chunk[cc];
            }
            int kk = 0;
            if (cc >= 0) {
                int bs = cc * per;
                for (int bb = bs + per - 1; bb >= bs; bb--) {
                    cum += fhist[bb];
                    if (cum >= KPRE) { kk = bb; break; }
                }
            }
            while (cum > KMAX && kk < FBINS - 1) { cum -= fhist[kk]; kk++; }
            s_kk = (unsigned int)kk;
        }
        __syncthreads();
        unsigned int kk = s_kk;
        __syncthreads();   // fhist reads done before keys (alias) writes
        for (int a = tid; a < A; a += SNT) {
            float s = scores[((size_t)b * A + a) * (size_t)C + c];
            if (g_valid[(size_t)b * A + a] && s > SCORE_THR) {
                unsigned int bin =
                    (unsigned int)min((int)(s * (float)FBINS), FBINS - 1);
                if (bin >= kk) {
                    unsigned int pos = atomicAdd(&s_m, 1u);
                    if (pos < KMAX)
                        keys[pos] =
                            ((unsigned long long)__float_as_uint(s) << 32) |
                            (unsigned long long)(0xFFFFFFFFu - (unsigned int)a);
                }
            }
        }
        __syncthreads();
    }

    unsigned int m = min(s_m, (unsigned int)KMAX);
    const int NSORT = (m <= 1024u) ? 1024 : 2048;
    for (int i = tid; i < NSORT; i += SNT)
        if (i >= (int)m) keys[i] = 0ULL;
    __syncthreads();

    for (int k = 2; k <= NSORT; k <<= 1) {
        for (int j = k >> 1; j > 0; j >>= 1) {
            for (int i = tid; i < NSORT; i += SNT) {
                int ixj = i ^ j;
                if (ixj > i) {
                    unsigned long long x = keys[i];
                    unsigned long long y = keys[ixj];
                    bool desc = ((i & k) == 0);
                    if (desc ? (x < y) : (x > y)) { keys[i] = y; keys[ixj] = x; }
                }
            }
            __syncthreads();
        }
    }

    // epilogue: write sorted keys + gathered boxes/areas
    {
        unsigned long long key = keys[tid];
        g_top[(size_t)bc * 512 + tid] = key;
        float s = __uint_as_float((unsigned int)(key >> 32));
        unsigned int aidx = 0xFFFFFFFFu - (unsigned int)(key & 0xFFFFFFFFull);
        float4 bx = make_float4(0.0f, 0.0f, 0.0f, 0.0f);
        if (s > SCORE_THR)
            bx = reinterpret_cast<const float4*>(g_boxes)[(size_t)b * A + aidx];
        g_cbox[(size_t)bc * 512 + tid]  = bx;
        g_carea[(size_t)bc * 512 + tid] = (bx.z - bx.x) * (bx.w - bx.y);
    }
}

// ---------------------------------------------------------------------------
// K4: IoU suppression bitmask. grid (BC, 8) x 256thr; warp = (row-group g,
// quarter q): computes chunks ch>=g with ch%4==q. Lower triangle never
// written (scan guards). Division-free compare.
// ---------------------------------------------------------------------------
__global__ void __launch_bounds__(256)
rn_iou(int C) {
    __shared__ float4 cbox[512];
    __shared__ float  carea[512];

    const int tid = threadIdx.x;
    const int bc  = blockIdx.x;

    for (int idx = tid; idx < 512; idx += 256) {
        cbox[idx]  = g_cbox[(size_t)bc * 512 + idx];
        carea[idx] = g_carea[(size_t)bc * 512 + idx];
    }
    __syncthreads();

    const int lane = tid & 31;
    const int widx = blockIdx.y * 8 + (tid >> 5);   // 0..63
    const int g    = widx >> 2;                      // row group 0..15
    const int q    = widx & 3;                       // chunk quarter
    const int i    = g * 32 + lane;
    const bool vi  = (i < KPRE);

    float4 bi = cbox[i];
    float  ai = carea[i];

    unsigned int* __restrict__ om = g_ioum + (size_t)bc * KPRE * 16;

    int ch0 = g + ((q - g) & 3);                     // smallest ch>=g, ch%4==q
    for (int ch = ch0; ch < 16; ch += 4) {
        unsigned int m = 0;
        int jbase = ch * 32;
        #pragma unroll 8
        for (int jj = 0; jj < 32; jj++) {
            int j = jbase + jj;                      // broadcast LDS
            float4 bj = cbox[j];
            float  aj = carea[j];
            float lx = fmaxf(bi.x, bj.x);
            float ly = fmaxf(bi.y, bj.y);
            float rx = fminf(bi.z, bj.z);
            float ry = fminf(bi.w, bj.w);
            float iw = fmaxf(rx - lx, 0.0f);
            float ih = fmaxf(ry - ly, 0.0f);
            float inter = iw * ih;
            float den = fmaxf(ai + aj - inter, 1e-9f);
            bool pred = (j > i) && (inter > NMS_THR * den);
            m |= ((unsigned int)pred) << jj;
        }
        if (vi) om[i * 16 + ch] = m;
    }
}

// ---------------------------------------------------------------------------
// K5: serial-semantics NMS scan + ranked output
// (lower-triangle mask words never written by K4 -> guarded by tid >= i>>5)
// ---------------------------------------------------------------------------
__global__ void __launch_bounds__(512)
rn_scan(float* __restrict__ out, int B, int A, int C) {
    __shared__ unsigned int ioum[KPRE * 16];   // 32000 B
    __shared__ float4       cbox[KPRE];        // 8000 B
    __shared__ float        cscore[KPRE];
    __shared__ unsigned int keep0[16], keepw[16], pref[16];
    __shared__ unsigned int s_nkeep;

    const int tid = threadIdx.x;
    const int bc  = blockIdx.x;

    if (tid < 16) keep0[tid] = 0;
    {
        const uint4* __restrict__ src =
            reinterpret_cast<const uint4*>(g_ioum + (size_t)bc * KPRE * 16);
        uint4* dst = reinterpret_cast<uint4*>(ioum);
        for (int i = tid; i < KPRE * 4; i += 512) dst[i] = src[i];
    }
    if (tid < KPRE) {
        unsigned long long key = g_top[(size_t)bc * 512 + tid];
        float s = __uint_as_float((unsigned int)(key >> 32));
        bool cv = (s > SCORE_THR);
        cscore[tid] = s;
        cbox[tid]   = g_cbox[(size_t)bc * 512 + tid];
        if (cv) atomicOr(&keep0[tid >> 5], 1u << (tid & 31));
    }
    __syncthreads();

    if (tid < 16) {
        unsigned int kw = keep0[tid];
        int kept = 0;
        for (int w = 0; w < 16 && kept < MAXDET; w++) {
            unsigned int p = 0;
            while (true) {
                unsigned int cur = __shfl_sync(0xFFFFu, kw, w);
                unsigned int rem = (p < 32u)
                    ? (cur & (p ? (0xFFFFFFFFu << p) : 0xFFFFFFFFu)) : 0u;
                if (!rem) break;
                int bit = __ffs(rem) - 1;
                int i = w * 32 + bit;
                if (tid >= w)                      // words below diagonal are 0
                    kw &= ~ioum[i * 16 + tid];
                kept++;
                if (kept >= MAXDET) break;
                p = (unsigned int)bit + 1u;
            }
        }
        keepw[tid] = kw;
        unsigned int pc = __popc(kw);
        unsigned int scan = pc;
        #pragma unroll
        for (int o = 1; o < 16; o <<= 1) {
            unsigned int v = __shfl_up_sync(0xFFFFu, scan, o);
            if (tid >= o) scan += v;
        }
        pref[tid] = scan - pc;
        if (tid == 15) s_nkeep = scan;
    }
    __syncthreads();

    float* outp = out + (size_t)bc * MAXDET * 5;
    if (tid < KPRE) {
        unsigned int kw = keepw[tid >> 5];
        if ((kw >> (tid & 31)) & 1u) {
            unsigned int rank = pref[tid >> 5] + __popc(kw & ((1u << (tid & 31)) - 1u));
            if (rank < MAXDET) {
                float4 bx = cbox[tid];
                outp[rank * 5 + 0] = bx.x;
                outp[rank * 5 + 1] = bx.y;
                outp[rank * 5 + 2] = bx.z;
                outp[rank * 5 + 3] = bx.w;
                outp[rank * 5 + 4] = cscore[tid];
            }
        }
    }
    unsigned int nk = min(s_nkeep, (unsigned int)MAXDET);
    for (int r = (int)nk + tid; r < MAXDET; r += 512) {
        outp[r * 5 + 0] = 0.0f;
        outp[r * 5 + 1] = 0.0f;
        outp[r * 5 + 2] = 0.0f;
        outp[r * 5 + 3] = 0.0f;
        outp[r * 5 + 4] = -1.0f;
    }
}

// ---------------------------------------------------------------------------
// host launch
// ---------------------------------------------------------------------------
extern "C" void kernel_launch(void* const* d_in, const int* in_sizes, int n_in,
                              void* d_out, int out_size) {
    const float* deltas  = (const float*)d_in[0];
    const float* scores  = (const float*)d_in[1];
    const float* anchors = (const float*)d_in[2];
    const int*   imh     = (const int*)d_in[3];
    const int*   imw     = (const int*)d_in[4];

    long long nd = in_sizes[0];
    long long ns = in_sizes[1];
    int C  = (int)(ns * 4 / nd);
    int BC = out_size / (MAXDET * 5);
    int B  = BC / C;
    int A  = (int)(nd / (4LL * B));

    float* out = (float*)d_out;

    int n = B * A;
    rn_decode<<<(n + 255) / 256, 256>>>(deltas, anchors, imh, imw, B, A);

    dim3 cg((A + CA - 1) / CA, B);
    rn_collect<<<cg, CANT>>>(scores, B, A, C);

    rn_sort<<<BC, SNT, 32768>>>(scores, B, A, C);
    rn_iou<<<dim3(BC, 8), 256>>>(C);
    rn_scan<<<BC, 512>>>(out, B, A, C);
}